// round 4
// baseline (speedup 1.0000x reference)
#include <cuda_runtime.h>
#include <cuda_bf16.h>
#include <cstdint>

#define NPTS 16384
#define NW   512          // NPTS/32 words per adjacency row
#define EPS2 0.04f
#define MINPTS 10
#define BIGV NPTS
#define ROWS_PER_BLOCK 32
#define TILE 2048

// -------- scratch (static device globals; no allocation) --------
__device__ unsigned g_adj[(size_t)NPTS * NW];   // 33.5 MB adjacency bitmask
__device__ unsigned g_corebits[NW];
__device__ int      g_core[NPTS];
__device__ float    g_sq[NPTS];
__device__ int      g_parent[NPTS];
__device__ int      g_compmin[NPTS];
__device__ int      g_rootc[NPTS];
__device__ int      g_labint[NPTS];
__device__ int      g_root[NPTS];
__device__ int      g_rank[NPTS];

// ---------------- k0: init + squared norms ----------------
__global__ void k0_init(const float* __restrict__ pts) {
    int i = blockIdx.x * blockDim.x + threadIdx.x;
    if (i < NW) g_corebits[i] = 0u;
    if (i < NPTS) {
        float x = pts[3*i], y = pts[3*i+1], z = pts[3*i+2];
        // match reference: sum(points*points, axis=1) -> (x*x + y*y) + z*z, no fma fusion
        g_sq[i] = __fadd_rn(__fadd_rn(__fmul_rn(x,x), __fmul_rn(y,y)), __fmul_rn(z,z));
        g_parent[i]  = i;
        g_compmin[i] = BIGV;
        g_core[i]    = 0;
    }
}

// ---------------- k1: adjacency bitmask + degree/core ----------------
// 512 blocks x 256 threads; each block handles 32 rows, 8 warps x 4 rows each.
// Points staged in smem tiles of 2048 float4 (x,y,z,sq).
__global__ void __launch_bounds__(256) k1_adj(const float* __restrict__ pts) {
    __shared__ float4 tile[TILE];
    const int w    = threadIdx.x >> 5;
    const int lane = threadIdx.x & 31;
    const int rbase = blockIdx.x * ROWS_PER_BLOCK;

    float rx[4], ry[4], rz[4], rs[4];
    int deg[4] = {0,0,0,0};
#pragma unroll
    for (int k = 0; k < 4; k++) {
        int r = rbase + w*4 + k;
        rx[k] = pts[3*r]; ry[k] = pts[3*r+1]; rz[k] = pts[3*r+2];
        rs[k] = g_sq[r];
    }

    for (int tb = 0; tb < NPTS; tb += TILE) {
        __syncthreads();
        for (int t = threadIdx.x; t < TILE; t += blockDim.x) {
            int j = tb + t;
            tile[t] = make_float4(pts[3*j], pts[3*j+1], pts[3*j+2], g_sq[j]);
        }
        __syncthreads();
        for (int jw = 0; jw < TILE/32; jw++) {
            float4 p = tile[jw*32 + lane];
            unsigned m[4];
#pragma unroll
            for (int k = 0; k < 4; k++) {
                // match reference: d2 = (sq_i + sq_j) - 2*dot, dot = (x*x'+y*y')+z*z'
                float dot = __fadd_rn(__fadd_rn(__fmul_rn(rx[k],p.x), __fmul_rn(ry[k],p.y)),
                                      __fmul_rn(rz[k],p.z));
                float d2  = __fsub_rn(__fadd_rn(rs[k], p.w), __fmul_rn(2.0f, dot));
                m[k] = __ballot_sync(0xffffffffu, d2 < EPS2);
            }
            if (lane == 0) {
                int wi = (tb >> 5) + jw;
#pragma unroll
                for (int k = 0; k < 4; k++) {
                    int r = rbase + w*4 + k;
                    g_adj[(size_t)r * NW + wi] = m[k];
                    deg[k] += __popc(m[k]);
                }
            }
        }
    }
    if (lane == 0) {
#pragma unroll
        for (int k = 0; k < 4; k++) {
            int r = rbase + w*4 + k;
            if (deg[k] >= MINPTS) {
                g_core[r] = 1;
                atomicOr(&g_corebits[r >> 5], 1u << (r & 31));
            }
        }
    }
}

// ---------------- union-find (lock-free, hook larger under smaller) ----------------
__device__ __forceinline__ int uf_find(int x) {
    int p = g_parent[x];
    while (p != x) {
        int gp = g_parent[p];
        if (gp != p) g_parent[x] = gp;   // path halving; benign race (values only decrease)
        x = p;
        p = gp;
    }
    return p;
}

__device__ __forceinline__ void uf_union(int a, int b) {
    int ra = uf_find(a), rb = uf_find(b);
    while (ra != rb) {
        if (ra > rb) { int t = ra; ra = rb; rb = t; }
        int old = atomicCAS(&g_parent[rb], rb, ra);
        if (old == rb) return;
        rb = uf_find(old);
        ra = uf_find(ra);
    }
}

// ---------------- k2: unions over core-core edges (j < i, each edge once) ----------------
__global__ void k2_union() {
    int gw   = (blockIdx.x * blockDim.x + threadIdx.x) >> 5;  // warp per row
    int lane = threadIdx.x & 31;
    if (gw >= NPTS) return;
    int row = gw;
    if (!g_core[row]) return;
    int wmax = row >> 5;
    for (int wi = lane; wi <= wmax; wi += 32) {
        unsigned word = g_adj[(size_t)row * NW + wi] & g_corebits[wi];
        if (wi == wmax) word &= (1u << (row & 31)) - 1u;   // strictly below diagonal
        while (word) {
            int b = __ffs(word) - 1;
            word &= word - 1u;
            uf_union(row, (wi << 5) + b);
        }
    }
}

// ---------------- k3: flatten roots + component min ----------------
__global__ void k3_flatten() {
    int i = blockIdx.x * blockDim.x + threadIdx.x;
    if (i >= NPTS || !g_core[i]) return;
    int r = uf_find(i);
    g_rootc[i] = r;
    atomicMin(&g_compmin[r], i);
}

// ---------------- k4: per-point core label ----------------
__global__ void k4_lab() {
    int i = blockIdx.x * blockDim.x + threadIdx.x;
    if (i >= NPTS) return;
    g_labint[i] = g_core[i] ? g_compmin[g_rootc[i]] : BIGV;
}

// ---------------- k5: every point's root = min label among core neighbors ----------------
__global__ void k5_border() {
    int gw   = (blockIdx.x * blockDim.x + threadIdx.x) >> 5;  // warp per row
    int lane = threadIdx.x & 31;
    if (gw >= NPTS) return;
    int minv = BIGV;
    const uint4* rowp = (const uint4*)(g_adj + (size_t)gw * NW);
    for (int c = lane; c < NW/4; c += 32) {
        uint4 a = rowp[c];
        int base = c * 4;
        unsigned w0 = a.x & g_corebits[base+0];
        unsigned w1 = a.y & g_corebits[base+1];
        unsigned w2 = a.z & g_corebits[base+2];
        unsigned w3 = a.w & g_corebits[base+3];
#define SCAN_WORD(wrd, bb) \
        while (wrd) { int b = __ffs(wrd)-1; wrd &= wrd-1u; \
                      int v = g_labint[((base+(bb))<<5) + b]; minv = min(minv, v); }
        SCAN_WORD(w0,0) SCAN_WORD(w1,1) SCAN_WORD(w2,2) SCAN_WORD(w3,3)
#undef SCAN_WORD
    }
    for (int o = 16; o; o >>= 1) minv = min(minv, __shfl_xor_sync(0xffffffffu, minv, o));
    if (lane == 0) g_root[gw] = minv;
}

// ---------------- k6: rank scan (renumber roots) + final labels ----------------
__global__ void __launch_bounds__(512) k6_finish(float* __restrict__ out) {
    __shared__ int ssum[512];
    int t = threadIdx.x;                 // 512 threads x 32 elements
    int base = t * 32;
    int cnt = 0;
#pragma unroll
    for (int k = 0; k < 32; k++) {
        int i = base + k;
        cnt += (g_core[i] && g_labint[i] == i) ? 1 : 0;
    }
    ssum[t] = cnt;
    __syncthreads();
    for (int o = 1; o < 512; o <<= 1) {
        int v = (t >= o) ? ssum[t - o] : 0;
        __syncthreads();
        ssum[t] += v;
        __syncthreads();
    }
    int run = (t > 0) ? ssum[t - 1] : 0;
#pragma unroll
    for (int k = 0; k < 32; k++) {
        int i = base + k;
        run += (g_core[i] && g_labint[i] == i) ? 1 : 0;
        g_rank[i] = run - 1;             // inclusive cumsum - 1
    }
    __syncthreads();                     // block-wide visibility of g_rank
#pragma unroll
    for (int k = 0; k < 32; k++) {
        int i = base + k;
        int r = g_root[i];
        out[i] = (r < BIGV) ? (float)g_rank[r] : -1.0f;
    }
}

// ---------------- launch ----------------
extern "C" void kernel_launch(void* const* d_in, const int* in_sizes, int n_in,
                              void* d_out, int out_size) {
    const float* pts = (const float*)d_in[0];
    float* out = (float*)d_out;
    (void)in_sizes; (void)n_in; (void)out_size;

    k0_init <<<(NPTS + 255) / 256, 256>>>(pts);
    k1_adj  <<<NPTS / ROWS_PER_BLOCK, 256>>>(pts);
    k2_union<<<NPTS / 8, 256>>>();       // warp per row
    k3_flatten<<<NPTS / 256, 256>>>();
    k4_lab    <<<NPTS / 256, 256>>>();
    k5_border <<<NPTS / 8, 256>>>();     // warp per row
    k6_finish <<<1, 512>>>(out);
}

// round 5
// speedup vs baseline: 1.4298x; 1.4298x over previous
#include <cuda_runtime.h>
#include <cuda_bf16.h>
#include <cstdint>

#define NPTS 16384
#define NW   512          // words per adjacency row
#define NT   512          // row tiles (NPTS/32)
#define EPS2 0.04f
#define MINPTS 10
#define BIGV NPTS

// -------- scratch (static device globals; no allocation) --------
// tile-major adjacency: ADJ(rt, w, l) = g_adj[(rt*512 + w)*32 + l], row = rt*32+l
__device__ unsigned g_adj[(size_t)NT * NW * 32];   // 33.5 MB
__device__ unsigned g_corebits[NW];
__device__ int      g_core[NPTS];
__device__ int      g_parent[NPTS];
__device__ int      g_compmin[NPTS];
__device__ int      g_rootc[NPTS];
__device__ int      g_root[NPTS];
__device__ int      g_rank[NPTS];

// ---------------- f32x2 packed helpers ----------------
typedef unsigned long long u64;
__device__ __forceinline__ u64 pack2(float lo, float hi) {
    u64 r; asm("mov.b64 %0, {%1, %2};" : "=l"(r) : "f"(lo), "f"(hi)); return r;
}
__device__ __forceinline__ void unpack2(u64 v, float& lo, float& hi) {
    asm("mov.b64 {%0, %1}, %2;" : "=f"(lo), "=f"(hi) : "l"(v));
}
__device__ __forceinline__ u64 mul2(u64 a, u64 b) {
    u64 d; asm("mul.rn.f32x2 %0, %1, %2;" : "=l"(d) : "l"(a), "l"(b)); return d;
}
__device__ __forceinline__ u64 add2(u64 a, u64 b) {
    u64 d; asm("add.rn.f32x2 %0, %1, %2;" : "=l"(d) : "l"(a), "l"(b)); return d;
}

// ---------------- 32x32 bit-matrix transpose (warp) ----------------
__device__ __forceinline__ unsigned bittranspose(unsigned x, int lane) {
    const unsigned msk[5] = {0xFFFF0000u, 0xFF00FF00u, 0xF0F0F0F0u, 0xCCCCCCCCu, 0xAAAAAAAAu};
#pragma unroll
    for (int k = 0; k < 5; k++) {
        int s = 16 >> k;
        unsigned m = msk[k];
        unsigned y = __shfl_xor_sync(0xffffffffu, x, s);
        if ((lane & s) == 0) x = (x & ~m) | ((y << s) & m);
        else                 x = (x &  m) | ((y >> s) & ~m);
    }
    return x;
}

// ---------------- k1: triangular adjacency with mirror-transpose ----------------
// grid 512 x 128 threads (4 warps). block b: pair p=b>>1, half h=b&1.
// tiles tA=p, tB=511-p; warp w handles chunk residues (h*4+w) mod 8.
// lane = row within tile; rows live in registers (pre-negated-doubled coords).
struct RowPack { u64 x2, y2, z2, s2; };

__device__ __forceinline__ RowPack load_rowpack(const float* __restrict__ pts, int r) {
    float x = pts[3*r], y = pts[3*r+1], z = pts[3*r+2];
    float s = __fadd_rn(__fadd_rn(__fmul_rn(x,x), __fmul_rn(y,y)), __fmul_rn(z,z));
    float xn = __fmul_rn(-2.0f, x);
    float yn = __fmul_rn(-2.0f, y);
    float zn = __fmul_rn(-2.0f, z);
    RowPack rp;
    rp.x2 = pack2(xn, xn); rp.y2 = pack2(yn, yn); rp.z2 = pack2(zn, zn); rp.s2 = pack2(s, s);
    return rp;
}

__device__ __forceinline__ unsigned tile_word(const RowPack& rp,
                                              const u64* jx, const u64* jy,
                                              const u64* jz, const u64* js) {
    unsigned wrd = 0;
#pragma unroll
    for (int q = 0; q < 16; q++) {
        u64 dotn = add2(add2(mul2(rp.x2, jx[q]), mul2(rp.y2, jy[q])), mul2(rp.z2, jz[q]));
        u64 d2   = add2(add2(rp.s2, js[q]), dotn);
        float lo, hi; unpack2(d2, lo, hi);
        if (lo < EPS2) wrd |= (1u << (2*q));
        if (hi < EPS2) wrd |= (1u << (2*q+1));
    }
    return wrd;
}

__global__ void __launch_bounds__(128) k1_adj(const float* __restrict__ pts) {
    __shared__ float4 sjA[4][16];   // {x0,x1,y0,y1} per j-pair
    __shared__ float4 sjB[4][16];   // {z0,z1,s0,s1}
    const int w    = threadIdx.x >> 5;
    const int lane = threadIdx.x & 31;
    const int p = blockIdx.x >> 1, h = blockIdx.x & 1;
    const int tA = p, tB = (NT - 1) - p;

    RowPack ra = load_rowpack(pts, tA*32 + lane);
    RowPack rb = load_rowpack(pts, tB*32 + lane);

    for (int jc = h*4 + w; jc <= tB; jc += 8) {
        // ---- stage 32 j points (lanes 0..15, 2 points each) ----
        if (lane < 16) {
            int j0 = jc*32 + 2*lane;
            const float2* pp = (const float2*)(pts + 3*j0);
            float2 a = pp[0], b = pp[1], c = pp[2];
            // x0=a.x y0=a.y z0=b.x | x1=b.y y1=c.x z1=c.y
            float s0 = __fadd_rn(__fadd_rn(__fmul_rn(a.x,a.x), __fmul_rn(a.y,a.y)), __fmul_rn(b.x,b.x));
            float s1 = __fadd_rn(__fadd_rn(__fmul_rn(b.y,b.y), __fmul_rn(c.x,c.x)), __fmul_rn(c.y,c.y));
            sjA[w][lane] = make_float4(a.x, b.y, a.y, c.x);
            sjB[w][lane] = make_float4(b.x, c.y, s0, s1);
        }
        __syncwarp();

        u64 jx[16], jy[16], jz[16], js[16];
#pragma unroll
        for (int q = 0; q < 16; q++) {
            float4 A = sjA[w][q], B = sjB[w][q];
            jx[q] = pack2(A.x, A.y); jy[q] = pack2(A.z, A.w);
            jz[q] = pack2(B.x, B.y); js[q] = pack2(B.z, B.w);
        }

        const bool doA = (jc <= tA);
        unsigned wB = tile_word(rb, jx, jy, jz, js);
        g_adj[(((tB << 9) + jc) << 5) + lane] = wB;
        if (jc < tB) {
            unsigned tw = bittranspose(wB, lane);
            g_adj[(((jc << 9) + tB) << 5) + lane] = tw;
        }
        if (doA) {
            unsigned wA = tile_word(ra, jx, jy, jz, js);
            g_adj[(((tA << 9) + jc) << 5) + lane] = wA;
            if (jc < tA) {
                unsigned tw = bittranspose(wA, lane);
                g_adj[(((jc << 9) + tA) << 5) + lane] = tw;
            }
        }
        __syncwarp();
    }
}

// ---------------- k1b: degree/core + init (coalesced popc pass) ----------------
__global__ void __launch_bounds__(256) k1b_deg() {
    __shared__ int part[8][32];
    int rt = blockIdx.x;
    int lane = threadIdx.x & 31, sl = threadIdx.x >> 5;
    const unsigned* basep = g_adj + ((size_t)rt << 14);
    int cnt = 0;
    for (int wi = sl; wi < NW; wi += 8)
        cnt += __popc(basep[(wi << 5) + lane]);
    part[sl][lane] = cnt;
    __syncthreads();
    if (threadIdx.x < 32) {
        int deg = 0;
#pragma unroll
        for (int s = 0; s < 8; s++) deg += part[s][lane];
        int row = (rt << 5) + lane;
        int c = (deg >= MINPTS) ? 1 : 0;
        g_core[row]    = c;
        g_parent[row]  = row;
        g_compmin[row] = BIGV;
        unsigned cb = __ballot_sync(0xffffffffu, c != 0);
        if (lane == 0) g_corebits[rt] = cb;
    }
}

// ---------------- union-find ----------------
__device__ __forceinline__ int uf_find(int x) {
    int pr = g_parent[x];
    while (pr != x) {
        int gp = g_parent[pr];
        if (gp != pr) g_parent[x] = gp;   // path halving; benign race
        x = pr;
        pr = gp;
    }
    return pr;
}

__device__ __forceinline__ void uf_union(int a, int b) {
    int ra = uf_find(a), rb = uf_find(b);
    while (ra != rb) {
        if (ra > rb) { int t = ra; ra = rb; rb = t; }
        int old = atomicCAS(&g_parent[rb], rb, ra);
        if (old == rb) return;
        rb = uf_find(old);
        ra = uf_find(ra);
    }
}

// ---------------- k2: unions over core-core edges (strictly lower triangle) ----------------
__global__ void __launch_bounds__(256) k2_union() {
    int rt = (NT - 1) - blockIdx.x;          // biggest row-tiles first
    int lane = threadIdx.x & 31, sl = threadIdx.x >> 5;
    int row = (rt << 5) + lane;
    if (!g_core[row]) return;
    const unsigned* basep = g_adj + ((size_t)rt << 14);
    for (int wi = sl; wi <= rt; wi += 8) {
        unsigned word = basep[(wi << 5) + lane] & g_corebits[wi];
        if (wi == rt) word &= (1u << lane) - 1u;   // j < row on diagonal tile
        while (word) {
            int b = __ffs(word) - 1;
            word &= word - 1u;
            uf_union(row, (wi << 5) + b);
        }
    }
}

// ---------------- k3: flatten roots + component min (original index) ----------------
__global__ void k3_flatten() {
    int i = blockIdx.x * blockDim.x + threadIdx.x;
    if (i >= NPTS || !g_core[i]) return;
    int r = uf_find(i);
    g_rootc[i] = r;
    atomicMin(&g_compmin[r], i);
}

// ---------------- k5: per-point min label among core neighbors ----------------
__global__ void __launch_bounds__(256) k5_border() {
    __shared__ int part[8][32];
    int rt = blockIdx.x;
    int lane = threadIdx.x & 31, sl = threadIdx.x >> 5;
    const unsigned* basep = g_adj + ((size_t)rt << 14);
    int mn = BIGV;
    for (int wi = sl; wi < NW; wi += 8) {
        unsigned word = basep[(wi << 5) + lane] & g_corebits[wi];
        while (word) {
            int b = __ffs(word) - 1;
            word &= word - 1u;
            int j = (wi << 5) + b;
            int v = g_compmin[g_rootc[j]];
            mn = min(mn, v);
        }
    }
    part[sl][lane] = mn;
    __syncthreads();
    if (threadIdx.x < 32) {
        int m = part[0][lane];
#pragma unroll
        for (int s = 1; s < 8; s++) m = min(m, part[s][lane]);
        g_root[(rt << 5) + lane] = m;
    }
}

// ---------------- k6: rank scan (renumber roots) + final labels ----------------
__global__ void __launch_bounds__(512) k6_finish(float* __restrict__ out) {
    __shared__ int ssum[512];
    int t = threadIdx.x;                 // 512 threads x 32 elements
    int base = t * 32;
    int cnt = 0;
#pragma unroll
    for (int k = 0; k < 32; k++) {
        int i = base + k;
        int isr = 0;
        if (g_core[i]) isr = (g_compmin[g_rootc[i]] == i) ? 1 : 0;
        cnt += isr;
    }
    ssum[t] = cnt;
    __syncthreads();
    for (int o = 1; o < 512; o <<= 1) {
        int v = (t >= o) ? ssum[t - o] : 0;
        __syncthreads();
        ssum[t] += v;
        __syncthreads();
    }
    int run = (t > 0) ? ssum[t - 1] : 0;
#pragma unroll
    for (int k = 0; k < 32; k++) {
        int i = base + k;
        int isr = 0;
        if (g_core[i]) isr = (g_compmin[g_rootc[i]] == i) ? 1 : 0;
        run += isr;
        g_rank[i] = run - 1;             // inclusive cumsum - 1
    }
    __syncthreads();
#pragma unroll
    for (int k = 0; k < 32; k++) {
        int i = base + k;
        int r = g_root[i];
        out[i] = (r < BIGV) ? (float)g_rank[r] : -1.0f;
    }
}

// ---------------- launch ----------------
extern "C" void kernel_launch(void* const* d_in, const int* in_sizes, int n_in,
                              void* d_out, int out_size) {
    const float* pts = (const float*)d_in[0];
    float* out = (float*)d_out;
    (void)in_sizes; (void)n_in; (void)out_size;

    k1_adj    <<<NT, 128>>>(pts);        // 512 blocks, balanced triangle pairs
    k1b_deg   <<<NT, 256>>>();
    k2_union  <<<NT, 256>>>();
    k3_flatten<<<NPTS / 256, 256>>>();
    k5_border <<<NT, 256>>>();
    k6_finish <<<1, 512>>>(out);
}

// round 6
// speedup vs baseline: 1.4480x; 1.0127x over previous
#include <cuda_runtime.h>
#include <cuda_bf16.h>
#include <cstdint>

#define NPTS 16384
#define NW   512          // words per adjacency row
#define NT   512          // row tiles (NPTS/32)
#define EPS2 0.04f
#define MINPTS 10
#define BIGV NPTS

// -------- scratch (static device globals; no allocation) --------
// tile-major adjacency: ADJ(rt, w, l) = g_adj[(rt*512 + w)*32 + l], row = rt*32+l
__device__ unsigned g_adj[(size_t)NT * NW * 32];   // 33.5 MB
__device__ unsigned g_corebits[NW];
__device__ int      g_core[NPTS];
__device__ int      g_parent[NPTS];
__device__ int      g_root[NPTS];
__device__ int      g_rank[NPTS];

// ---------------- f32x2 packed helpers ----------------
typedef unsigned long long u64;
__device__ __forceinline__ u64 pack2(float lo, float hi) {
    u64 r; asm("mov.b64 %0, {%1, %2};" : "=l"(r) : "f"(lo), "f"(hi)); return r;
}
__device__ __forceinline__ u64 mul2(u64 a, u64 b) {
    u64 d; asm("mul.rn.f32x2 %0, %1, %2;" : "=l"(d) : "l"(a), "l"(b)); return d;
}
__device__ __forceinline__ u64 add2(u64 a, u64 b) {
    u64 d; asm("add.rn.f32x2 %0, %1, %2;" : "=l"(d) : "l"(a), "l"(b)); return d;
}

// ---------------- 32x32 bit-matrix transpose (warp) ----------------
__device__ __forceinline__ unsigned bittranspose(unsigned x, int lane) {
    const unsigned msk[5] = {0xFFFF0000u, 0xFF00FF00u, 0xF0F0F0F0u, 0xCCCCCCCCu, 0xAAAAAAAAu};
#pragma unroll
    for (int k = 0; k < 5; k++) {
        int s = 16 >> k;
        unsigned m = msk[k];
        unsigned y = __shfl_xor_sync(0xffffffffu, x, s);
        if ((lane & s) == 0) x = (x & ~m) | ((y << s) & m);
        else                 x = (x &  m) | ((y >> s) & ~m);
    }
    return x;
}

// ---------------- k1: triangular adjacency with mirror-transpose ----------------
// grid 512 x 128 threads (4 warps). block b: pair p=b>>1, half h=b&1.
// tiles tA=p, tB=511-p; warp w handles chunk residues (h*4+w) mod 8.
// lane = row within tile; row constants (-2x,-2y,-2z,sq) packed in registers.
// j points staged as pre-packed u64 quads in shared (broadcast LDS in q loop).
struct RowPack { u64 x2, y2, z2, s2; };

__device__ __forceinline__ RowPack load_rowpack(const float* __restrict__ pts, int r) {
    float x = pts[3*r], y = pts[3*r+1], z = pts[3*r+2];
    float s = __fadd_rn(__fadd_rn(__fmul_rn(x,x), __fmul_rn(y,y)), __fmul_rn(z,z));
    float xn = __fmul_rn(-2.0f, x);
    float yn = __fmul_rn(-2.0f, y);
    float zn = __fmul_rn(-2.0f, z);
    RowPack rp;
    rp.x2 = pack2(xn, xn); rp.y2 = pack2(yn, yn); rp.z2 = pack2(zn, zn); rp.s2 = pack2(s, s);
    return rp;
}

__device__ __forceinline__ unsigned tile_word(const RowPack& rp, const u64* __restrict__ sj,
                                              u64 negeps) {
    unsigned wrd = 0;
#pragma unroll
    for (int q = 0; q < 16; q++) {
        const u64* e = sj + q*4;
        u64 jx = e[0], jy = e[1], jz = e[2], js = e[3];
        u64 dotn = add2(add2(mul2(rp.x2, jx), mul2(rp.y2, jy)), mul2(rp.z2, jz));
        u64 d2   = add2(add2(rp.s2, js), dotn);
        u64 v    = add2(d2, negeps);          // sign bit <=> d2 < EPS2 (exact for strict <)
        unsigned lo, hi;
        asm("mov.b64 {%0, %1}, %2;" : "=r"(lo), "=r"(hi) : "l"(v));
        wrd |= (lo >> 31) << (2*q);
        wrd |= (hi >> 31) << (2*q + 1);
    }
    return wrd;
}

__global__ void __launch_bounds__(128) k1_adj(const float* __restrict__ pts) {
    __shared__ __align__(16) u64 sj[4][16][4];   // [warp][q][x2,y2,z2,s2]
    const int w    = threadIdx.x >> 5;
    const int lane = threadIdx.x & 31;
    const int p = blockIdx.x >> 1, h = blockIdx.x & 1;
    const int tA = p, tB = (NT - 1) - p;
    const u64 negeps = pack2(-EPS2, -EPS2);

    RowPack ra = load_rowpack(pts, tA*32 + lane);
    RowPack rb = load_rowpack(pts, tB*32 + lane);

    for (int jc = h*4 + w; jc <= tB; jc += 8) {
        // ---- stage 32 j points as packed pairs (lanes 0..15, 2 points each) ----
        if (lane < 16) {
            int j0 = jc*32 + 2*lane;
            const float2* pp = (const float2*)(pts + 3*j0);
            float2 a = pp[0], b = pp[1], c = pp[2];
            // x0=a.x y0=a.y z0=b.x | x1=b.y y1=c.x z1=c.y
            float s0 = __fadd_rn(__fadd_rn(__fmul_rn(a.x,a.x), __fmul_rn(a.y,a.y)), __fmul_rn(b.x,b.x));
            float s1 = __fadd_rn(__fadd_rn(__fmul_rn(b.y,b.y), __fmul_rn(c.x,c.x)), __fmul_rn(c.y,c.y));
            u64* dst = sj[w][lane];
            dst[0] = pack2(a.x, b.y);
            dst[1] = pack2(a.y, c.x);
            dst[2] = pack2(b.x, c.y);
            dst[3] = pack2(s0, s1);
        }
        __syncwarp();

        unsigned wB = tile_word(rb, &sj[w][0][0], negeps);
        g_adj[(((tB << 9) + jc) << 5) + lane] = wB;
        if (jc < tB) {
            unsigned tw = bittranspose(wB, lane);
            g_adj[(((jc << 9) + tB) << 5) + lane] = tw;
        }
        if (jc <= tA) {
            unsigned wA = tile_word(ra, &sj[w][0][0], negeps);
            g_adj[(((tA << 9) + jc) << 5) + lane] = wA;
            if (jc < tA) {
                unsigned tw = bittranspose(wA, lane);
                g_adj[(((jc << 9) + tA) << 5) + lane] = tw;
            }
        }
        __syncwarp();
    }
}

// ---------------- k1b: degree/core + init (coalesced popc pass) ----------------
__global__ void __launch_bounds__(256) k1b_deg() {
    __shared__ int part[8][32];
    int rt = blockIdx.x;
    int lane = threadIdx.x & 31, sl = threadIdx.x >> 5;
    const unsigned* basep = g_adj + ((size_t)rt << 14);
    int cnt = 0;
    for (int wi = sl; wi < NW; wi += 8)
        cnt += __popc(basep[(wi << 5) + lane]);
    part[sl][lane] = cnt;
    __syncthreads();
    if (threadIdx.x < 32) {
        int deg = 0;
#pragma unroll
        for (int s = 0; s < 8; s++) deg += part[s][lane];
        int row = (rt << 5) + lane;
        int c = (deg >= MINPTS) ? 1 : 0;
        g_core[row]   = c;
        g_parent[row] = row;
        unsigned cb = __ballot_sync(0xffffffffu, c != 0);
        if (lane == 0) g_corebits[rt] = cb;
    }
}

// ---------------- union-find (hook larger root under smaller =>
//                  final root of each component is its minimum index) ----------------
__device__ __forceinline__ int uf_find(int x) {
    int pr = g_parent[x];
    while (pr != x) {
        int gp = g_parent[pr];
        if (gp != pr) g_parent[x] = gp;   // path halving; benign race
        x = pr;
        pr = gp;
    }
    return pr;
}

__device__ __forceinline__ void uf_union(int a, int b) {
    int ra = uf_find(a), rb = uf_find(b);
    while (ra != rb) {
        if (ra > rb) { int t = ra; ra = rb; rb = t; }
        int old = atomicCAS(&g_parent[rb], rb, ra);
        if (old == rb) return;
        rb = uf_find(old);
        ra = uf_find(ra);
    }
}

// ---------------- k2: unions over core-core edges (strictly lower triangle) ----------------
__global__ void __launch_bounds__(256) k2_union() {
    int rt = (NT - 1) - blockIdx.x;          // biggest row-tiles first
    int lane = threadIdx.x & 31, sl = threadIdx.x >> 5;
    int row = (rt << 5) + lane;
    if (!g_core[row]) return;
    const unsigned* basep = g_adj + ((size_t)rt << 14);
    for (int wi = sl; wi <= rt; wi += 8) {
        unsigned word = basep[(wi << 5) + lane] & g_corebits[wi];
        if (wi == rt) word &= (1u << lane) - 1u;   // j < row on diagonal tile
        while (word) {
            int b = __ffs(word) - 1;
            word &= word - 1u;
            uf_union(row, (wi << 5) + b);
        }
    }
}

// ---------------- k5: per-point min root among core neighbors (inline find) ----------------
__global__ void __launch_bounds__(256) k5_border() {
    __shared__ int part[8][32];
    int rt = blockIdx.x;
    int lane = threadIdx.x & 31, sl = threadIdx.x >> 5;
    const unsigned* basep = g_adj + ((size_t)rt << 14);
    int mn = BIGV;
    for (int wi = sl; wi < NW; wi += 8) {
        unsigned word = basep[(wi << 5) + lane] & g_corebits[wi];
        while (word) {
            int b = __ffs(word) - 1;
            word &= word - 1u;
            int v = uf_find((wi << 5) + b);   // root == component min
            mn = min(mn, v);
        }
    }
    part[sl][lane] = mn;
    __syncthreads();
    if (threadIdx.x < 32) {
        int m = part[0][lane];
#pragma unroll
        for (int s = 1; s < 8; s++) m = min(m, part[s][lane]);
        g_root[(rt << 5) + lane] = m;
    }
}

// ---------------- k6: rank scan (renumber roots) + final labels ----------------
__global__ void __launch_bounds__(512) k6_finish(float* __restrict__ out) {
    __shared__ int ssum[512];
    int t = threadIdx.x;                 // 512 threads x 32 elements
    int base = t * 32;
    int cnt = 0;
#pragma unroll
    for (int k = 0; k < 32; k++) {
        int i = base + k;
        cnt += (g_core[i] && g_parent[i] == i) ? 1 : 0;   // component root
    }
    ssum[t] = cnt;
    __syncthreads();
    for (int o = 1; o < 512; o <<= 1) {
        int v = (t >= o) ? ssum[t - o] : 0;
        __syncthreads();
        ssum[t] += v;
        __syncthreads();
    }
    int run = (t > 0) ? ssum[t - 1] : 0;
#pragma unroll
    for (int k = 0; k < 32; k++) {
        int i = base + k;
        run += (g_core[i] && g_parent[i] == i) ? 1 : 0;
        g_rank[i] = run - 1;             // inclusive cumsum - 1
    }
    __syncthreads();
#pragma unroll
    for (int k = 0; k < 32; k++) {
        int i = base + k;
        int r = g_root[i];
        out[i] = (r < BIGV) ? (float)g_rank[r] : -1.0f;
    }
}

// ---------------- launch ----------------
extern "C" void kernel_launch(void* const* d_in, const int* in_sizes, int n_in,
                              void* d_out, int out_size) {
    const float* pts = (const float*)d_in[0];
    float* out = (float*)d_out;
    (void)in_sizes; (void)n_in; (void)out_size;

    k1_adj    <<<NT, 128>>>(pts);        // 512 blocks, balanced triangle pairs
    k1b_deg   <<<NT, 256>>>();
    k2_union  <<<NT, 256>>>();
    k5_border <<<NT, 256>>>();
    k6_finish <<<1, 512>>>(out);
}